// round 6
// baseline (speedup 1.0000x reference)
#include <cuda_runtime.h>
#include <cstddef>

#define HH 512
#define WW 512
#define CC 64
#define HWSZ (HH*WW)
#define KS 576
#define WQ_SIZE 36864
#define MAGF 12582912.0f           // 1.5 * 2^23 -> round-half-even via magic add
#define MAGBITS 0x4B400000u        // bit pattern of MAGF

// ---------------- scratch (no allocations allowed) ----------------
__device__ float g_part[9 * 64 * 64];   // [kk][c][hb] per-block partial act maxes
__device__ float g_qm2[9 * 64];         // [k][c] : 1/(scale_j * s_x)
__device__ float g_sx;                  // s_x

// ---------------- K1: per-(c,kh,kw) activation abs-max partials ----------------
// (R4 version verbatim: measured 16.0 us, regs=26, 4 front-batched LDG.128/thread)
__global__ __launch_bounds__(256) void k1_actmax(const float* __restrict__ in) {
    int c    = blockIdx.x;          // 64
    int hb   = blockIdx.y;          // 64 groups of 8 rows
    int warp = threadIdx.x >> 5;
    int lane = threadIdx.x & 31;

    const float* row = in + (size_t)c * HWSZ + (size_t)(hb * 8 + warp) * WW + lane * 16;
    float v[16];
#pragma unroll
    for (int i = 0; i < 4; i++) {
        float4 t = *(const float4*)(row + i * 4);
        v[i*4+0] = fabsf(t.x); v[i*4+1] = fabsf(t.y);
        v[i*4+2] = fabsf(t.z); v[i*4+3] = fabsf(t.w);
    }
    float mMid = v[1];
#pragma unroll
    for (int i = 2; i < 15; i++) mMid = fmaxf(mMid, v[i]);

    // core = max over this row's interior cols (0<w<511); borders tracked separately
    float core;
    if (lane == 0)       core = fmaxf(mMid, v[15]);
    else if (lane == 31) core = fmaxf(mMid, v[0]);
    else                 core = fmaxf(fmaxf(mMid, v[0]), v[15]);

    __shared__ float s_core[8], s_v0[8], s_v511[8];
    if (lane == 0)  s_v0[warp]   = v[0];      // col 0 (abs)
    if (lane == 31) s_v511[warp] = v[15];     // col 511 (abs)
    unsigned r = __reduce_max_sync(0xffffffffu, (unsigned)__float_as_int(core));
    if (lane == 0) s_core[warp] = __int_as_float((int)r);
    __syncthreads();

    if (threadIdx.x < 9) {
        int kh = threadIdx.x / 3, kw = threadIdx.x % 3;
        int r0 = (kh == 2 && hb == 0)  ? 1 : 0;   // kh=2 excludes global row 0
        int r1 = (kh == 0 && hb == 63) ? 7 : 8;   // kh=0 excludes global row 511
        float mx = 0.f;
        for (int rr = r0; rr < r1; rr++) {
            float t = s_core[rr];
            if (kw != 2) t = fmaxf(t, s_v0[rr]);     // kw 0,1 include col 0
            if (kw != 0) t = fmaxf(t, s_v511[rr]);   // kw 1,2 include col 511
            mx = fmaxf(mx, t);
        }
        g_part[threadIdx.x * 4096 + c * 64 + hb] = mx;
    }
}

// ---------------- K2: reduce partials, scales, s_x, s_w, quantized weight ----------------
__global__ __launch_bounds__(576) void k2_scales(const float* __restrict__ wgt,
                                                 float* __restrict__ out_wq) {
    int j = threadIdx.x;            // j = c*9 + kk
    int c = j / 9, kk = j % 9;
    __shared__ float sA[18], sW[18];
    __shared__ float sh_ax, sh_aw;

    float act = 0.f;
    const float* pp = g_part + kk * 4096 + c * 64;
#pragma unroll 8
    for (int r = 0; r < 64; r++) act = fmaxf(act, pp[r]);

    float wmax = 0.f;
#pragma unroll 8
    for (int co = 0; co < 64; co++)
        wmax = fmaxf(wmax, fabsf(wgt[co * KS + j]));

    float scale = sqrtf(act) / sqrtf(wmax);   // alpha = 0.5
    if (scale == 0.f) scale = 1.f;
    float candx = act / scale;                // column max of |x/scale|
    float candw = wmax * scale;               // column max of |w*scale|

    unsigned rx = __reduce_max_sync(0xffffffffu, (unsigned)__float_as_int(candx));
    unsigned rw = __reduce_max_sync(0xffffffffu, (unsigned)__float_as_int(candw));
    if ((j & 31) == 0) { sA[j >> 5] = __int_as_float((int)rx);
                         sW[j >> 5] = __int_as_float((int)rw); }
    __syncthreads();
    if (j == 0) {
        float ax = 0.f, aw = 0.f;
        for (int r = 0; r < 18; r++) { ax = fmaxf(ax, sA[r]); aw = fmaxf(aw, sW[r]); }
        sh_ax = ax; sh_aw = aw;
    }
    __syncthreads();

    float sx = (sh_ax > 0.f) ? (sh_ax / 127.0f) : 1.f;
    float sw = (sh_aw > 0.f) ? (sh_aw / 127.0f) : 1.f;

    g_qm2[kk * 64 + c] = 1.0f / (scale * sx);   // [k][c] layout for k3
    if (j == 0) g_sx = sx;

    int kh = kk / 3, kw = kk % 3;
    float inv_sw = 1.0f / sw;
#pragma unroll 4
    for (int co = 0; co < 64; co++) {
        float wv = wgt[co * KS + j] * scale;
        float q  = rintf(fminf(fmaxf(wv * inv_sw, -127.f), 127.f));
        out_wq[((co * 3 + kh) * 3 + kw) * 64 + c] = q * sw;
    }
}

// ---------------- tap sum via integer-bits accumulation ----------------
// t_k = RN(v*m_k + MAG) lies in [2^23, 2^24)  =>  bits(t_k) = MAGBITS + round(v*m_k)
// with |round(v*m_k)| <= 127.  Sum the 9 bit patterns with wrapping u32 adds
// (ptxas fuses into IADD3 on the ALU pipe, dual-issuing with the FFMAs),
// subtract 8*MAGBITS: result bits = MAGBITS + Sum r_k; reinterpret and subtract
// MAG (exact, same binade).  Masked taps (m=0) give bits exactly MAGBITS -> 0.
__device__ __forceinline__ float taps9i(float v, const float* m) {
    unsigned s = 0u;
#pragma unroll
    for (int k = 0; k < 9; k++)
        s += __float_as_uint(fmaf(v, m[k], MAGF));
    s -= 8u * MAGBITS;                 // wrapping; true value fits in 32 bits
    return __uint_as_float(s) - MAGF;  // = (float)Sum_k round(v*m_k), exact
}

// ---------------- K3: fused quantize + fold + NCHW->NHWC ----------------
// (R1 structure verbatim — measured 39 us — with taps9i replacing the fp chain)
// xf[h,w,c] = s_x * Sum_{valid (kh,kw)} round( input[c,h,w] * qm[c,kh,kw] )
__global__ __launch_bounds__(256) void k3_fold(const float* __restrict__ in,
                                               float* __restrict__ out) {
    __shared__ float s_in[CC][33];     // stride 33: conflict-free both phases
    __shared__ float s_qm[KS];         // copy of g_qm2 ([k][c] layout)

    const int h   = blockIdx.y;        // 512
    const int wt  = blockIdx.x;        // 16 tiles of 32 pixels
    const int tid = threadIdx.x;

    for (int i = tid; i < KS; i += 256) s_qm[i] = g_qm2[i];

    // Load 64 channels x 32 w-pixels of row h (coalesced float4 reads)
    const float* base = in + (size_t)h * WW + wt * 32;
    for (int i = tid; i < 512; i += 256) {
        int cc = i >> 3, w4 = i & 7;
        float4 t = *(const float4*)(base + (size_t)cc * HWSZ + w4 * 4);
        s_in[cc][w4 * 4 + 0] = t.x;
        s_in[cc][w4 * 4 + 1] = t.y;
        s_in[cc][w4 * 4 + 2] = t.z;
        s_in[cc][w4 * 4 + 3] = t.w;
    }
    __syncthreads();

    const float sx = g_sx;
    const int c  = tid & 63;
    const int g  = tid >> 6;           // 0..3, 8 pixels each
    const int w0 = wt * 32 + g * 8;

    float m[9];
#pragma unroll
    for (int k = 0; k < 9; k++) m[k] = s_qm[k * 64 + c];   // [k][c]: conflict-free
    if (h == 0)      { m[6] = 0.f; m[7] = 0.f; m[8] = 0.f; }  // kh=2 invalid
    if (h == HH - 1) { m[0] = 0.f; m[1] = 0.f; m[2] = 0.f; }  // kh=0 invalid

    float res[8];
    const bool wedge = (w0 == 0) | (w0 + 7 == WW - 1);     // warp-uniform

    if (!wedge) {
#pragma unroll
        for (int p = 0; p < 8; p++)
            res[p] = taps9i(s_in[c][g * 8 + p], m) * sx;
    } else {
#pragma unroll
        for (int p = 0; p < 8; p++) {
            int w = w0 + p;
            float mm[9];
#pragma unroll
            for (int k = 0; k < 9; k++) mm[k] = m[k];
            if (w == 0)      { mm[2] = 0.f; mm[5] = 0.f; mm[8] = 0.f; }  // kw=2 @ w=0
            if (w == WW - 1) { mm[0] = 0.f; mm[3] = 0.f; mm[6] = 0.f; }  // kw=0 @ w=511
            res[p] = taps9i(s_in[c][g * 8 + p], mm) * sx;
        }
    }

    float* o = out + ((size_t)(h * WW + w0)) * 64 + c;
#pragma unroll
    for (int p = 0; p < 8; p++) o[p * 64] = res[p];
}

// ---------------- launch ----------------
extern "C" void kernel_launch(void* const* d_in, const int* in_sizes, int n_in,
                              void* d_out, int out_size) {
    const float* inp = (const float*)d_in[0];
    const float* wgt = (const float*)d_in[1];
    if (n_in >= 2 && in_sizes[0] == WQ_SIZE) {   // defensive: swap if order differs
        const float* t = inp; inp = wgt; wgt = t;
    }
    float* out_wq = (float*)d_out;
    float* out_xf = (float*)d_out + WQ_SIZE;

    {
        dim3 grid(64, 64);
        k1_actmax<<<grid, 256>>>(inp);
    }
    k2_scales<<<1, 576>>>(wgt, out_wq);
    {
        dim3 grid(16, 512);
        k3_fold<<<grid, 256>>>(inp, out_xf);
    }
}